// round 4
// baseline (speedup 1.0000x reference)
#include <cuda_runtime.h>
#include <cstdint>
#include <math_constants.h>

#define N_NODES   8192
#define NODE_DIM  512
#define HID       256
#define NCLS      16
#define NEDGE     262144
#define MASKW     (N_NODES / 32)   // 256 words per row

// ---------------- scratch (device globals; no allocation allowed) ----------
__device__ uint32_t g_mask[N_NODES * MASKW];   // 8 MB adjacency bitmask
__device__ float    g_h[N_NODES * HID];        // 8 MB  h = x @ W^T
__device__ float    g_f1[N_NODES];
__device__ float    g_f2[N_NODES];

// ---------------- helpers ----------------------------------------------------
__device__ __forceinline__ float warpSum(float v) {
#pragma unroll
    for (int o = 16; o > 0; o >>= 1) v += __shfl_xor_sync(0xffffffffu, v, o);
    return v;
}
__device__ __forceinline__ float warpMax(float v) {
#pragma unroll
    for (int o = 16; o > 0; o >>= 1) v = fmaxf(v, __shfl_xor_sync(0xffffffffu, v, o));
    return v;
}

// packed fp32x2 math (Blackwell sm_103a; 2x fp32 per issue slot)
__device__ __forceinline__ unsigned long long fma2(unsigned long long a,
                                                   unsigned long long b,
                                                   unsigned long long c) {
    unsigned long long d;
    asm("fma.rn.f32x2 %0, %1, %2, %3;" : "=l"(d) : "l"(a), "l"(b), "l"(c));
    return d;
}
__device__ __forceinline__ unsigned long long pack2(float lo, float hi) {
    unsigned long long r;
    asm("mov.b64 %0, {%1, %2};" : "=l"(r) : "f"(lo), "f"(hi));
    return r;
}
__device__ __forceinline__ void unpack2(unsigned long long v, float& lo, float& hi) {
    asm("mov.b64 {%0, %1}, %2;" : "=f"(lo), "=f"(hi) : "l"(v));
}

// ---------------- 1. zero the bitmask ---------------------------------------
__global__ void zero_mask_kernel() {
    int idx = blockIdx.x * blockDim.x + threadIdx.x;
    int stride = gridDim.x * blockDim.x;
    uint4 z = make_uint4(0u, 0u, 0u, 0u);
    uint4* p = (uint4*)g_mask;
    for (int i = idx; i < N_NODES * MASKW / 4; i += stride) p[i] = z;
}

// ---------------- 2. build adjacency bitmask (dedupes automatically) --------
// Inline int64/int32 detection: int64 little-endian with values < 8192 means
// every odd 32-bit word of the first 64 is zero; int32 words are random node
// ids -> essentially never all zero. Uniform, L2-broadcast reads.
__global__ void build_mask_kernel(const void* __restrict__ edges) {
    const uint32_t* e32 = (const uint32_t*)edges;
    int is64 = 1;
#pragma unroll
    for (int k = 1; k < 64; k += 2)
        if (e32[k] != 0u) is64 = 0;

    int k = blockIdx.x * blockDim.x + threadIdx.x;
    if (k < NEDGE) {
        int r, c;
        if (is64) {
            const long long* p = (const long long*)edges;
            r = (int)p[k];
            c = (int)p[NEDGE + k];
        } else {
            const int* p = (const int*)edges;
            r = p[k];
            c = p[NEDGE + k];
        }
        atomicOr(&g_mask[r * MASKW + (c >> 5)], 1u << (c & 31));
    } else if (k < NEDGE + N_NODES) {
        int i = k - NEDGE;   // self loop
        atomicOr(&g_mask[i * MASKW + (i >> 5)], 1u << (i & 31));
    }
}

// ---------------- 3. h = x @ W^T  (fp32x2 double-buffered GEMM) --------------
// x: [N, 512] row-major, W: [256, 512] row-major, h: [N, 256]
// BM=128, BN=128, BK=16; 256 threads; 8x8 microtile = 4 row-pairs x 8 cols of
// packed f32x2 accumulators. 2-stage SMEM pipeline with register staging.
#define BM 128
#define BN 128
#define BK 16
#define AS_LD 132
#define BS_LD 132

__global__ void __launch_bounds__(256) gemm_kernel(const float* __restrict__ x,
                                                   const float* __restrict__ W) {
    __shared__ float As[2][BK][AS_LD];   // [buf][k][m]
    __shared__ float Bs[2][BK][BS_LD];   // [buf][k][n]

    const int bm = blockIdx.x * BM;
    const int bn = blockIdx.y * BN;
    const int tid = threadIdx.x;
    const int col0 = (tid & 15) * 8;     // 16 col groups x 8
    const int row0 = (tid >> 4) * 8;     // 16 row groups x 8

    const int lrow = tid >> 2;           // 0..63
    const int lkq  = tid & 3;            // 0..3 (k quad)

    unsigned long long acc[4][8];        // [row-pair][col]
#pragma unroll
    for (int i = 0; i < 4; i++)
#pragma unroll
        for (int j = 0; j < 8; j++) acc[i][j] = 0ull;

    const float* aptr0 = &x[(size_t)(bm + lrow) * NODE_DIM + lkq * 4];
    const float* aptr1 = &x[(size_t)(bm + lrow + 64) * NODE_DIM + lkq * 4];
    const float* bptr0 = &W[(size_t)(bn + lrow) * NODE_DIM + lkq * 4];
    const float* bptr1 = &W[(size_t)(bn + lrow + 64) * NODE_DIM + lkq * 4];

    // prologue: stage tile 0
    float4 ra0 = *(const float4*)aptr0;
    float4 ra1 = *(const float4*)aptr1;
    float4 rb0 = *(const float4*)bptr0;
    float4 rb1 = *(const float4*)bptr1;
    {
        float* a = &As[0][lkq * 4][0];
        a[0 * AS_LD + lrow] = ra0.x; a[1 * AS_LD + lrow] = ra0.y;
        a[2 * AS_LD + lrow] = ra0.z; a[3 * AS_LD + lrow] = ra0.w;
        a[0 * AS_LD + lrow + 64] = ra1.x; a[1 * AS_LD + lrow + 64] = ra1.y;
        a[2 * AS_LD + lrow + 64] = ra1.z; a[3 * AS_LD + lrow + 64] = ra1.w;
        float* b = &Bs[0][lkq * 4][0];
        b[0 * BS_LD + lrow] = rb0.x; b[1 * BS_LD + lrow] = rb0.y;
        b[2 * BS_LD + lrow] = rb0.z; b[3 * BS_LD + lrow] = rb0.w;
        b[0 * BS_LD + lrow + 64] = rb1.x; b[1 * BS_LD + lrow + 64] = rb1.y;
        b[2 * BS_LD + lrow + 64] = rb1.z; b[3 * BS_LD + lrow + 64] = rb1.w;
    }
    __syncthreads();

    const int NTILES = NODE_DIM / BK;    // 32
    for (int t = 0; t < NTILES; t++) {
        const int cur = t & 1;
        const int nxt = cur ^ 1;
        const bool have_next = (t + 1) < NTILES;
        if (have_next) {
            int off = (t + 1) * BK;
            ra0 = *(const float4*)(aptr0 + off);
            ra1 = *(const float4*)(aptr1 + off);
            rb0 = *(const float4*)(bptr0 + off);
            rb1 = *(const float4*)(bptr1 + off);
        }

#pragma unroll
        for (int k = 0; k < BK; k++) {
            const unsigned long long* ap =
                (const unsigned long long*)&As[cur][k][row0];
            unsigned long long a0 = ap[0], a1 = ap[1], a2 = ap[2], a3 = ap[3];
            float4 bv0 = *(const float4*)&Bs[cur][k][col0];
            float4 bv1 = *(const float4*)&Bs[cur][k][col0 + 4];
            unsigned long long b[8];
            b[0] = pack2(bv0.x, bv0.x); b[1] = pack2(bv0.y, bv0.y);
            b[2] = pack2(bv0.z, bv0.z); b[3] = pack2(bv0.w, bv0.w);
            b[4] = pack2(bv1.x, bv1.x); b[5] = pack2(bv1.y, bv1.y);
            b[6] = pack2(bv1.z, bv1.z); b[7] = pack2(bv1.w, bv1.w);

#pragma unroll
            for (int j = 0; j < 8; j++) {
                acc[0][j] = fma2(a0, b[j], acc[0][j]);
                acc[1][j] = fma2(a1, b[j], acc[1][j]);
                acc[2][j] = fma2(a2, b[j], acc[2][j]);
                acc[3][j] = fma2(a3, b[j], acc[3][j]);
            }
        }

        if (have_next) {
            float* a = &As[nxt][lkq * 4][0];
            a[0 * AS_LD + lrow] = ra0.x; a[1 * AS_LD + lrow] = ra0.y;
            a[2 * AS_LD + lrow] = ra0.z; a[3 * AS_LD + lrow] = ra0.w;
            a[0 * AS_LD + lrow + 64] = ra1.x; a[1 * AS_LD + lrow + 64] = ra1.y;
            a[2 * AS_LD + lrow + 64] = ra1.z; a[3 * AS_LD + lrow + 64] = ra1.w;
            float* b = &Bs[nxt][lkq * 4][0];
            b[0 * BS_LD + lrow] = rb0.x; b[1 * BS_LD + lrow] = rb0.y;
            b[2 * BS_LD + lrow] = rb0.z; b[3 * BS_LD + lrow] = rb0.w;
            b[0 * BS_LD + lrow + 64] = rb1.x; b[1 * BS_LD + lrow + 64] = rb1.y;
            b[2 * BS_LD + lrow + 64] = rb1.z; b[3 * BS_LD + lrow + 64] = rb1.w;
        }
        __syncthreads();
    }

    // epilogue: unpack row-pairs, store 2x float4 per row
#pragma unroll
    for (int rp = 0; rp < 4; rp++) {
        float lo[8], hi[8];
#pragma unroll
        for (int j = 0; j < 8; j++) unpack2(acc[rp][j], lo[j], hi[j]);
        int mlo = bm + row0 + rp * 2;
        *(float4*)&g_h[(size_t)mlo * HID + bn + col0] =
            make_float4(lo[0], lo[1], lo[2], lo[3]);
        *(float4*)&g_h[(size_t)mlo * HID + bn + col0 + 4] =
            make_float4(lo[4], lo[5], lo[6], lo[7]);
        *(float4*)&g_h[(size_t)(mlo + 1) * HID + bn + col0] =
            make_float4(hi[0], hi[1], hi[2], hi[3]);
        *(float4*)&g_h[(size_t)(mlo + 1) * HID + bn + col0 + 4] =
            make_float4(hi[4], hi[5], hi[6], hi[7]);
    }
}

// ---------------- 4. f1 = h@a1, f2 = h@a2 ------------------------------------
__global__ void __launch_bounds__(256) f1f2_kernel(const float* __restrict__ a1,
                                                   const float* __restrict__ a2) {
    int i = blockIdx.x;
    int t = threadIdx.x;
    float v = g_h[(size_t)i * HID + t];
    float s1 = v * a1[t];
    float s2 = v * a2[t];
    s1 = warpSum(s1);
    s2 = warpSum(s2);
    __shared__ float r1[8], r2[8];
    int warp = t >> 5, lane = t & 31;
    if (lane == 0) { r1[warp] = s1; r2[warp] = s2; }
    __syncthreads();
    if (warp == 0) {
        float x1 = (lane < 8) ? r1[lane] : 0.f;
        float x2 = (lane < 8) ? r2[lane] : 0.f;
        x1 = warpSum(x1);
        x2 = warpSum(x2);
        if (lane == 0) { g_f1[i] = x1; g_f2[i] = x2; }
    }
}

// ---------------- 5. fused per-row: softmax + SpMM + ELU + FC ----------------
#define MAXDEG 1024
__global__ void __launch_bounds__(256) gat_kernel(const float* __restrict__ fc_w,
                                                  const float* __restrict__ fc_b,
                                                  float* __restrict__ out) {
    const int i = blockIdx.x;
    const int t = threadIdx.x;
    const int warp = t >> 5, lane = t & 31;

    __shared__ int   nbr[MAXDEG];
    __shared__ float ew[MAXDEG];
    __shared__ float red[8];
    __shared__ float osm[HID];
    __shared__ int   wcnt[8];
    __shared__ int   woff[9];
    __shared__ float s_bcast;

    // ---- deterministic neighbor enumeration via block prefix-sum ----
    uint32_t w = g_mask[i * MASKW + t];
    int pc = __popc(w);
    int incl = pc;
#pragma unroll
    for (int o = 1; o < 32; o <<= 1) {
        int n = __shfl_up_sync(0xffffffffu, incl, o);
        if (lane >= o) incl += n;
    }
    if (lane == 31) wcnt[warp] = incl;
    __syncthreads();
    if (t == 0) {
        int s = 0;
#pragma unroll
        for (int q = 0; q < 8; q++) { woff[q] = s; s += wcnt[q]; }
        woff[8] = s;
    }
    __syncthreads();
    int base = woff[warp] + (incl - pc);
    {
        uint32_t ww = w;
        while (ww && base < MAXDEG) {
            int b = __ffs(ww) - 1;
            ww &= ww - 1;
            nbr[base++] = t * 32 + b;
        }
    }
    __syncthreads();
    const int deg = min(woff[8], MAXDEG);

    // ---- pass 1: leaky-relu scores + row max over nonzero scores ----
    const float f1i = g_f1[i];
    float lmax = -CUDART_INF_F;
    for (int k = t; k < deg; k += 256) {
        int j = nbr[k];
        float s = f1i + g_f2[j];
        s = (s > 0.f) ? s : 0.01f * s;
        ew[k] = s;
        if (s != 0.f) lmax = fmaxf(lmax, s);
    }
    lmax = warpMax(lmax);
    if (lane == 0) red[warp] = lmax;
    __syncthreads();
    if (t == 0) {
        float m = red[0];
#pragma unroll
        for (int q = 1; q < 8; q++) m = fmaxf(m, red[q]);
        s_bcast = m;
    }
    __syncthreads();
    const float mx = s_bcast;
    __syncthreads();

    // ---- pass 2: exp weights + sum (exact-zero scores are masked) ----
    float lsum = 0.f;
    for (int k = t; k < deg; k += 256) {
        float s = ew[k];
        float e = (s == 0.f) ? 0.f : __expf(s - mx);
        ew[k] = e;
        lsum += e;
    }
    lsum = warpSum(lsum);
    if (lane == 0) red[warp] = lsum;
    __syncthreads();
    if (t == 0) {
        float sm = 0.f;
#pragma unroll
        for (int q = 0; q < 8; q++) sm += red[q];
        s_bcast = sm;
    }
    __syncthreads();
    const float inv = 1.f / s_bcast;

    // ---- pass 3: weighted aggregation; thread t owns hidden dim t ----
    float acc = 0.f;
    int k = 0;
    for (; k + 4 <= deg; k += 4) {
        int j0 = nbr[k + 0], j1 = nbr[k + 1], j2 = nbr[k + 2], j3 = nbr[k + 3];
        float e0 = ew[k + 0], e1 = ew[k + 1], e2 = ew[k + 2], e3 = ew[k + 3];
        float h0 = g_h[(size_t)j0 * HID + t];
        float h1 = g_h[(size_t)j1 * HID + t];
        float h2 = g_h[(size_t)j2 * HID + t];
        float h3 = g_h[(size_t)j3 * HID + t];
        acc += e0 * h0 + e1 * h1 + e2 * h2 + e3 * h3;
    }
    for (; k < deg; k++) acc += ew[k] * g_h[(size_t)nbr[k] * HID + t];
    acc *= inv;

    // ELU
    float o = (acc > 0.f) ? acc : expm1f(acc);
    osm[t] = o;
    __syncthreads();

    // tiny FC: 16 classes, 8 warps -> 2 classes per warp
    for (int c = warp; c < NCLS; c += 8) {
        float s = 0.f;
#pragma unroll
        for (int d = lane; d < HID; d += 32) s += osm[d] * fc_w[c * HID + d];
        s = warpSum(s);
        if (lane == 0) out[i * NCLS + c] = s + fc_b[c];
    }
}

// ---------------- launch -----------------------------------------------------
extern "C" void kernel_launch(void* const* d_in, const int* in_sizes, int n_in,
                              void* d_out, int out_size) {
    const float* x    = (const float*)d_in[0];
    const void*  ei   = d_in[1];
    const float* W    = (const float*)d_in[2];
    const float* a1   = (const float*)d_in[3];
    const float* a2   = (const float*)d_in[4];
    const float* fc_w = (const float*)d_in[5];
    const float* fc_b = (const float*)d_in[6];
    float* out = (float*)d_out;

    zero_mask_kernel<<<1024, 256>>>();
    build_mask_kernel<<<(NEDGE + N_NODES + 255) / 256, 256>>>(ei);
    gemm_kernel<<<dim3(N_NODES / BM, HID / BN), 256>>>(x, W);
    f1f2_kernel<<<N_NODES, 256>>>(a1, a2);
    gat_kernel<<<N_NODES, 256>>>(fc_w, fc_b, out);
}

// round 11
// speedup vs baseline: 1.3617x; 1.3617x over previous
#include <cuda_runtime.h>
#include <cuda_bf16.h>
#include <mma.h>
#include <cstdint>
#include <math_constants.h>

using namespace nvcuda;

#define N_NODES   8192
#define NODE_DIM  512
#define HID       256
#define NCLS      16
#define NEDGE     262144
#define MASKW     (N_NODES / 32)   // 256 words per row

// ---------------- scratch (device globals; no allocation allowed) ----------
__device__ uint32_t g_mask[N_NODES * MASKW];                       // 8 MB
__device__ float    g_h[N_NODES * HID];                            // 8 MB
__device__ float    g_f1[N_NODES];
__device__ float    g_f2[N_NODES];
__device__ __align__(16) __nv_bfloat16 g_xh[N_NODES * NODE_DIM];   // 8 MB
__device__ __align__(16) __nv_bfloat16 g_xl[N_NODES * NODE_DIM];   // 8 MB
__device__ __align__(16) __nv_bfloat16 g_wh[HID * NODE_DIM];       // 256 KB
__device__ __align__(16) __nv_bfloat16 g_wl[HID * NODE_DIM];       // 256 KB

// ---------------- helpers ----------------------------------------------------
__device__ __forceinline__ float warpSum(float v) {
#pragma unroll
    for (int o = 16; o > 0; o >>= 1) v += __shfl_xor_sync(0xffffffffu, v, o);
    return v;
}
__device__ __forceinline__ float warpMax(float v) {
#pragma unroll
    for (int o = 16; o > 0; o >>= 1) v = fmaxf(v, __shfl_xor_sync(0xffffffffu, v, o));
    return v;
}
__device__ __forceinline__ uint32_t smem_u32(const void* p) {
    uint32_t a;
    asm("{ .reg .u64 t; cvta.to.shared.u64 t, %1; cvt.u32.u64 %0, t; }"
        : "=r"(a) : "l"(p));
    return a;
}
#define CP_ASYNC16(dst, src) \
    asm volatile("cp.async.cg.shared.global [%0], [%1], 16;" \
                 :: "r"(dst), "l"(src))
#define CP_COMMIT() asm volatile("cp.async.commit_group;" ::: "memory")
#define CP_WAIT2()  asm volatile("cp.async.wait_group 2;" ::: "memory")
#define CP_WAIT0()  asm volatile("cp.async.wait_group 0;" ::: "memory")

// bf16 split helpers
__device__ __forceinline__ uint32_t packbf_hi(float a, float b, float& ra, float& rb) {
    __nv_bfloat16 ha = __float2bfloat16_rn(a);
    __nv_bfloat16 hb = __float2bfloat16_rn(b);
    ra = a - __bfloat162float(ha);
    rb = b - __bfloat162float(hb);
    __nv_bfloat162 p; p.x = ha; p.y = hb;
    return *reinterpret_cast<uint32_t*>(&p);
}
__device__ __forceinline__ uint32_t packbf(float a, float b) {
    __nv_bfloat162 p;
    p.x = __float2bfloat16_rn(a);
    p.y = __float2bfloat16_rn(b);
    return *reinterpret_cast<uint32_t*>(&p);
}

// ---------------- 1. zero mask + f1/f2 ---------------------------------------
__global__ void zero_kernel() {
    int idx = blockIdx.x * blockDim.x + threadIdx.x;
    int stride = gridDim.x * blockDim.x;
    uint4 z = make_uint4(0u, 0u, 0u, 0u);
    uint4* p = (uint4*)g_mask;
    for (int i = idx; i < N_NODES * MASKW / 4; i += stride) p[i] = z;
    float4 fz = make_float4(0.f, 0.f, 0.f, 0.f);
    float4* q1 = (float4*)g_f1;
    float4* q2 = (float4*)g_f2;
    for (int i = idx; i < N_NODES / 4; i += stride) { q1[i] = fz; q2[i] = fz; }
}

// ---------------- 2. build adjacency bitmask (dedupes automatically) --------
__global__ void build_mask_kernel(const void* __restrict__ edges) {
    const uint32_t* e32 = (const uint32_t*)edges;
    int is64 = 1;
#pragma unroll
    for (int k = 1; k < 64; k += 2)
        if (e32[k] != 0u) is64 = 0;

    int k = blockIdx.x * blockDim.x + threadIdx.x;
    if (k < NEDGE) {
        int r, c;
        if (is64) {
            const long long* p = (const long long*)edges;
            r = (int)p[k];
            c = (int)p[NEDGE + k];
        } else {
            const int* p = (const int*)edges;
            r = p[k];
            c = p[NEDGE + k];
        }
        atomicOr(&g_mask[r * MASKW + (c >> 5)], 1u << (c & 31));
    } else if (k < NEDGE + N_NODES) {
        int i = k - NEDGE;   // self loop
        atomicOr(&g_mask[i * MASKW + (i >> 5)], 1u << (i & 31));
    }
}

// ---------------- 3. fp32 -> split-bf16 staging (x and W in one kernel) ------
#define XGROUPS (N_NODES * NODE_DIM / 8)   // 524288
#define WGROUPS (HID * NODE_DIM / 8)       // 16384
__global__ void __launch_bounds__(256) prep_kernel(const float* __restrict__ x,
                                                   const float* __restrict__ W) {
    int idx = blockIdx.x * blockDim.x + threadIdx.x;
    const float* src;
    uint4 *dh, *dl;
    int gi;
    if (idx < XGROUPS) {
        gi = idx;
        src = x + (size_t)gi * 8;
        dh = (uint4*)g_xh; dl = (uint4*)g_xl;
    } else {
        gi = idx - XGROUPS;
        if (gi >= WGROUPS) return;
        src = W + (size_t)gi * 8;
        dh = (uint4*)g_wh; dl = (uint4*)g_wl;
    }
    float4 v0 = *(const float4*)src;
    float4 v1 = *(const float4*)(src + 4);
    float r0, r1, r2, r3, r4, r5, r6, r7;
    uint4 H, L;
    H.x = packbf_hi(v0.x, v0.y, r0, r1);
    H.y = packbf_hi(v0.z, v0.w, r2, r3);
    H.z = packbf_hi(v1.x, v1.y, r4, r5);
    H.w = packbf_hi(v1.z, v1.w, r6, r7);
    L.x = packbf(r0, r1); L.y = packbf(r2, r3);
    L.z = packbf(r4, r5); L.w = packbf(r6, r7);
    dh[gi] = H;
    dl[gi] = L;
}

// ---------------- 4. h = x @ W^T  (wmma split-bf16, 3-stage cp.async) --------
// BM=128, BN=128, BK=32; 256 threads = 8 warps (4 m x 2 n), warptile 32x64.
// acc += Ah*Bh + Ah*Bl + Al*Bh  (fp32 accum). Epilogue fuses f1/f2 partials.
#define APITCH 40                     // bf16 elems per SMEM row (80 B)
#define TILE_B (128 * APITCH * 2)     // 10240 bytes per tile
#define NSTAGE 3
#define AOFF   0
#define BOFF   (2 * NSTAGE * TILE_B)  // 61440
#define A1OFF  (4 * NSTAGE * TILE_B)  // 122880 (also > Cs epilogue 67584)
#define A2OFF  (A1OFF + 512)
#define SMEM_GEMM (A2OFF + 512)       // 123904

__global__ void __launch_bounds__(256) wmma_gemm_kernel(const float* __restrict__ a1,
                                                        const float* __restrict__ a2) {
    extern __shared__ char sm[];
    const uint32_t sbase = smem_u32(sm);
    const int tid = threadIdx.x;
    const int wid = tid >> 5;
    const int bm = blockIdx.x * 128;
    const int bn = blockIdx.y * 128;
    const int wm = wid >> 1, wn = wid & 1;

    float* s_a1 = (float*)(sm + A1OFF);
    float* s_a2 = (float*)(sm + A2OFF);
    if (tid < 128) { s_a1[tid] = a1[bn + tid]; s_a2[tid] = a2[bn + tid]; }

    wmma::fragment<wmma::accumulator, 16, 16, 16, float> acc[2][4];
#pragma unroll
    for (int r = 0; r < 2; r++)
#pragma unroll
        for (int n = 0; n < 4; n++) wmma::fill_fragment(acc[r][n], 0.f);

    const int row = tid >> 2;         // 0..63 (x2 chunks)
    const int seg = tid & 3;          // 16B segment within 64B row-chunk

    // stage copy: 4 arrays x 512 chunks of 16B; 2 chunks/thread/array
    auto stage_copy = [&](int s, int kt) {
        const __nv_bfloat16* srcs[4] = {
            g_xh + (size_t)bm * NODE_DIM + kt,
            g_xl + (size_t)bm * NODE_DIM + kt,
            g_wh + (size_t)bn * NODE_DIM + kt,
            g_wl + (size_t)bn * NODE_DIM + kt };
        uint32_t dsts[4] = {
            sbase + AOFF + (uint32_t)(s * 2 + 0) * TILE_B,
            sbase + AOFF + (uint32_t)(s * 2 + 1) * TILE_B,
            sbase + BOFF + (uint32_t)(s * 2 + 0) * TILE_B,
            sbase + BOFF + (uint32_t)(s * 2 + 1) * TILE_B };
#pragma unroll
        for (int a = 0; a < 4; a++) {
#pragma unroll
            for (int i = 0; i < 2; i++) {
                int rr = row + i * 64;
                uint32_t dst = dsts[a] + (uint32_t)rr * 80 + (uint32_t)seg * 16;
                const void* src = srcs[a] + ((size_t)rr << 9) + seg * 8;
                CP_ASYNC16(dst, src);
            }
        }
    };

    const int NIT = NODE_DIM / 32;    // 16
    stage_copy(0, 0);
    CP_COMMIT();
    stage_copy(1, 32);
    CP_COMMIT();

    for (int t = 0; t < NIT; t++) {
        if (t + 2 < NIT) {
            stage_copy((t + 2) % NSTAGE, (t + 2) * 32);
            CP_COMMIT();
            CP_WAIT2();               // current stage (t) is complete
        } else {
            CP_WAIT0();
        }
        __syncthreads();

        const int s = t % NSTAGE;
        const __nv_bfloat16* Ah = (const __nv_bfloat16*)(sm + AOFF + (s * 2 + 0) * TILE_B);
        const __nv_bfloat16* Al = (const __nv_bfloat16*)(sm + AOFF + (s * 2 + 1) * TILE_B);
        const __nv_bfloat16* Bh = (const __nv_bfloat16*)(sm + BOFF + (s * 2 + 0) * TILE_B);
        const __nv_bfloat16* Bl = (const __nv_bfloat16*)(sm + BOFF + (s * 2 + 1) * TILE_B);

#pragma unroll
        for (int k16 = 0; k16 < 2; k16++) {
            wmma::fragment<wmma::matrix_a, 16, 16, 16, __nv_bfloat16, wmma::row_major> ah[2], al[2];
#pragma unroll
            for (int r = 0; r < 2; r++) {
                wmma::load_matrix_sync(ah[r], Ah + (wm * 32 + r * 16) * APITCH + k16 * 16, APITCH);
                wmma::load_matrix_sync(al[r], Al + (wm * 32 + r * 16) * APITCH + k16 * 16, APITCH);
            }
#pragma unroll
            for (int n = 0; n < 4; n++) {
                wmma::fragment<wmma::matrix_b, 16, 16, 16, __nv_bfloat16, wmma::col_major> bh, bl;
                wmma::load_matrix_sync(bh, Bh + (wn * 64 + n * 16) * APITCH + k16 * 16, APITCH);
                wmma::load_matrix_sync(bl, Bl + (wn * 64 + n * 16) * APITCH + k16 * 16, APITCH);
#pragma unroll
                for (int r = 0; r < 2; r++) {
                    wmma::mma_sync(acc[r][n], ah[r], bh, acc[r][n]);
                    wmma::mma_sync(acc[r][n], ah[r], bl, acc[r][n]);
                    wmma::mma_sync(acc[r][n], al[r], bh, acc[r][n]);
                }
            }
        }
        __syncthreads();
    }

    // ---- epilogue: store h; stage C in SMEM for fused f1/f2 partials ----
    float* Cs = (float*)sm;           // 128 x 132 floats = 67584 B (< A1OFF)
#pragma unroll
    for (int r = 0; r < 2; r++)
#pragma unroll
        for (int n = 0; n < 4; n++) {
            wmma::store_matrix_sync(
                &g_h[(size_t)(bm + wm * 32 + r * 16) * HID + bn + wn * 64 + n * 16],
                acc[r][n], HID, wmma::mem_row_major);
            wmma::store_matrix_sync(
                &Cs[(wm * 32 + r * 16) * 132 + wn * 64 + n * 16],
                acc[r][n], 132, wmma::mem_row_major);
        }
    __syncthreads();

    const int crow = tid >> 1;
    const int half = tid & 1;
    float p1 = 0.f, p2 = 0.f;
    const float* cr = &Cs[crow * 132 + half * 64];
#pragma unroll
    for (int d = 0; d < 64; d++) {
        float v = cr[d];
        p1 += v * s_a1[half * 64 + d];
        p2 += v * s_a2[half * 64 + d];
    }
    p1 += __shfl_down_sync(0xffffffffu, p1, 1);
    p2 += __shfl_down_sync(0xffffffffu, p2, 1);
    if (!half) {
        atomicAdd(&g_f1[bm + crow], p1);   // exactly 2 commutative adds -> deterministic
        atomicAdd(&g_f2[bm + crow], p2);
    }
}

// ---------------- 5. fused per-row: softmax + SpMM + ELU + FC ----------------
#define MAXDEG 1024
__global__ void __launch_bounds__(256) gat_kernel(const float* __restrict__ fc_w,
                                                  const float* __restrict__ fc_b,
                                                  float* __restrict__ out) {
    const int i = blockIdx.x;
    const int t = threadIdx.x;
    const int warp = t >> 5, lane = t & 31;

    __shared__ int   nbr[MAXDEG];
    __shared__ float ew[MAXDEG];
    __shared__ float red[8];
    __shared__ float osm[HID];
    __shared__ int   wcnt[8];
    __shared__ int   woff[9];
    __shared__ float s_bcast;

    // ---- deterministic neighbor enumeration via block prefix-sum ----
    uint32_t w = g_mask[i * MASKW + t];
    int pc = __popc(w);
    int incl = pc;
#pragma unroll
    for (int o = 1; o < 32; o <<= 1) {
        int n = __shfl_up_sync(0xffffffffu, incl, o);
        if (lane >= o) incl += n;
    }
    if (lane == 31) wcnt[warp] = incl;
    __syncthreads();
    if (t == 0) {
        int s = 0;
#pragma unroll
        for (int q = 0; q < 8; q++) { woff[q] = s; s += wcnt[q]; }
        woff[8] = s;
    }
    __syncthreads();
    int base = woff[warp] + (incl - pc);
    {
        uint32_t ww = w;
        while (ww && base < MAXDEG) {
            int b = __ffs(ww) - 1;
            ww &= ww - 1;
            nbr[base++] = t * 32 + b;
        }
    }
    __syncthreads();
    const int deg = min(woff[8], MAXDEG);

    // ---- pass 1: leaky-relu scores + row max over nonzero scores ----
    const float f1i = g_f1[i];
    float lmax = -CUDART_INF_F;
    for (int k = t; k < deg; k += 256) {
        int j = nbr[k];
        float s = f1i + g_f2[j];
        s = (s > 0.f) ? s : 0.01f * s;
        ew[k] = s;
        if (s != 0.f) lmax = fmaxf(lmax, s);
    }
    lmax = warpMax(lmax);
    if (lane == 0) red[warp] = lmax;
    __syncthreads();
    if (t == 0) {
        float m = red[0];
#pragma unroll
        for (int q = 1; q < 8; q++) m = fmaxf(m, red[q]);
        s_bcast = m;
    }
    __syncthreads();
    const float mx = s_bcast;
    __syncthreads();

    // ---- pass 2: exp weights + sum (exact-zero scores are masked) ----
    float lsum = 0.f;
    for (int k = t; k < deg; k += 256) {
        float s = ew[k];
        float e = (s == 0.f) ? 0.f : __expf(s - mx);
        ew[k] = e;
        lsum += e;
    }
    lsum = warpSum(lsum);
    if (lane == 0) red[warp] = lsum;
    __syncthreads();
    if (t == 0) {
        float sm = 0.f;
#pragma unroll
        for (int q = 0; q < 8; q++) sm += red[q];
        s_bcast = sm;
    }
    __syncthreads();
    const float inv = 1.f / s_bcast;

    // ---- pass 3: weighted aggregation; thread t owns hidden dim t ----
    float acc = 0.f;
    int k = 0;
    for (; k + 4 <= deg; k += 4) {
        int j0 = nbr[k + 0], j1 = nbr[k + 1], j2 = nbr[k + 2], j3 = nbr[k + 3];
        float e0 = ew[k + 0], e1 = ew[k + 1], e2 = ew[k + 2], e3 = ew[k + 3];
        float h0 = g_h[(size_t)j0 * HID + t];
        float h1 = g_h[(size_t)j1 * HID + t];
        float h2 = g_h[(size_t)j2 * HID + t];
        float h3 = g_h[(size_t)j3 * HID + t];
        acc += e0 * h0 + e1 * h1 + e2 * h2 + e3 * h3;
    }
    for (; k < deg; k++) acc += ew[k] * g_h[(size_t)nbr[k] * HID + t];
    acc *= inv;

    // ELU
    float o = (acc > 0.f) ? acc : expm1f(acc);
    osm[t] = o;
    __syncthreads();

    // tiny FC: 16 classes, 8 warps -> 2 classes per warp
    for (int c = warp; c < NCLS; c += 8) {
        float s = 0.f;
#pragma unroll
        for (int d = lane; d < HID; d += 32) s += osm[d] * fc_w[c * HID + d];
        s = warpSum(s);
        if (lane == 0) out[i * NCLS + c] = s + fc_b[c];
    }
}

// ---------------- launch -----------------------------------------------------
extern "C" void kernel_launch(void* const* d_in, const int* in_sizes, int n_in,
                              void* d_out, int out_size) {
    const float* x    = (const float*)d_in[0];
    const void*  ei   = d_in[1];
    const float* W    = (const float*)d_in[2];
    const float* a1   = (const float*)d_in[3];
    const float* a2   = (const float*)d_in[4];
    const float* fc_w = (const float*)d_in[5];
    const float* fc_b = (const float*)d_in[6];
    float* out = (float*)d_out;

    cudaFuncSetAttribute(wmma_gemm_kernel,
                         cudaFuncAttributeMaxDynamicSharedMemorySize, SMEM_GEMM);

    zero_kernel<<<1024, 256>>>();
    build_mask_kernel<<<(NEDGE + N_NODES + 255) / 256, 256>>>(ei);
    prep_kernel<<<(XGROUPS + WGROUPS + 255) / 256, 256>>>(x, W);
    wmma_gemm_kernel<<<dim3(N_NODES / 128, HID / 128), 256, SMEM_GEMM>>>(a1, a2);
    gat_kernel<<<N_NODES, 256>>>(fc_w, fc_b, out);
}